// round 2
// baseline (speedup 1.0000x reference)
#include <cuda_runtime.h>
#include <cuda_fp16.h>
#include <stdint.h>

// Problem constants (fixed by the dataset)
#define BATCH   32
#define HDIM    4096     // hidden dim (K of gemm1, N of gemm2)
#define IDIM    2048     // intermediate (K of gemm2)
#define NCOLS   4096     // N of both GEMMs (2*I for gemm1, H for gemm2)
#define GSZ     128      // quant group size

// Tiling
#define NT      64       // columns per block
#define KC      32       // K per chunk (one smem stage)
#define KSPLIT  4        // K-split factor (deterministic partials)
#define THREADS 256

// NOTE: harness promotes float16 reference arrays to float32.
// x, gate_up_scales, down_scales, and the output are all float32.

// ---------------- scratch (__device__ globals; no allocation allowed) ----
__device__ float g_xT[HDIM * BATCH];              // x transposed, f32 [k][b]
__device__ float g_actT[IDIM * BATCH];            // SwiGLU act transposed [i][b]
__device__ float g_hpart[KSPLIT][BATCH * NCOLS];  // gemm1 partials
__device__ float g_opart[KSPLIT][BATCH * NCOLS];  // gemm2 partials

// ---------------- packed f32x2 helpers ----------------------------------
__device__ __forceinline__ unsigned long long pack2(float lo, float hi) {
    unsigned long long r;
    asm("mov.b64 %0, {%1, %2};" : "=l"(r) : "f"(lo), "f"(hi));
    return r;
}
__device__ __forceinline__ unsigned long long fma2(unsigned long long a,
                                                   unsigned long long b,
                                                   unsigned long long c) {
    unsigned long long d;
    asm("fma.rn.f32x2 %0, %1, %2, %3;" : "=l"(d) : "l"(a), "l"(b), "l"(c));
    return d;
}

// FP4 E2M1 nibble -> f32, scaled by 2^-14 (caller folds 2^14 into scale).
// fp16 bit pattern (s<<15)|(eem<<9) == fp4_value * 2^-14 exactly, including
// the e=0 subnormal cases (0, 0.5). cvt.f32.f16 is exact.
__device__ __forceinline__ float fp4_raw(uint32_t nib) {
    uint32_t hb = ((nib & 8u) << 12) | ((nib & 7u) << 9);
    return __half2float(__ushort_as_half((unsigned short)hb));
}

// ---------------- kernel 0: x [B][H] f32 -> xT [H][B] f32 ----------------
__global__ void __launch_bounds__(THREADS) transpose_x_kernel(const float* __restrict__ x) {
    int idx = blockIdx.x * THREADS + threadIdx.x;   // over HDIM*BATCH
    int k = idx >> 5;
    int b = idx & 31;
    g_xT[idx] = x[b * HDIM + k];
}

// ---------------- fused dequant-GEMM (both phases) -----------------------
// out_part[split][b][n] = sum_{k in split} xT[k][b] * dequant(W[k][n])
// lane = batch row b; warp handles 8 columns; block handles NT=64 columns.
template <int KDIM, bool PHASE1>
__global__ void __launch_bounds__(THREADS) gemm_dq_kernel(
    const int*   __restrict__ packed,   // [KDIM/8][NCOLS]
    const float* __restrict__ scales)   // [KDIM/GSZ][NCOLS] (f32, harness-promoted)
{
    __shared__ __align__(16) float wsh[KC][NT];   // 8 KB dequantized tile

    const float* __restrict__ xT = PHASE1 ? g_xT : g_actT;

    const int tid  = threadIdx.x;
    const int lane = tid & 31;     // batch row
    const int warp = tid >> 5;     // 8 warps
    const int n_base  = blockIdx.x * NT;
    const int kspan   = KDIM / KSPLIT;
    const int k_begin = blockIdx.y * kspan;
    const int nchunks = kspan / KC;

    // dequant assignment: 4 word-rows x 64 cols = 256 words per chunk, 1/thread
    const int dq_row = tid >> 6;        // 0..3
    const int dq_col = tid & 63;        // 0..63
    const int dq_n   = n_base + dq_col;

    const int n0 = warp * 8;            // this warp's 8 columns within tile

    unsigned long long acc0 = 0ull, acc1 = 0ull, acc2 = 0ull, acc3 = 0ull;

    for (int c = 0; c < nchunks; ++c) {
        const int k0 = k_begin + c * KC;

        // coalesced x loads for this chunk (issued early, overlap dequant)
        float xv[KC];
        #pragma unroll
        for (int i = 0; i < KC; ++i)
            xv[i] = xT[(k0 + i) * BATCH + lane];

        // cooperative dequant of one packed word (8 FP4 values) per thread
        {
            const int k8 = (k0 >> 3) + dq_row;
            const uint32_t word = (uint32_t)packed[k8 * NCOLS + dq_n];
            const float sf = scales[(k8 >> 4) * NCOLS + dq_n] * 16384.0f;
            #pragma unroll
            for (int j = 0; j < 8; ++j) {
                uint32_t nib = (word >> (4 * j)) & 0xFu;
                wsh[dq_row * 8 + j][dq_col] = fp4_raw(nib) * sf;
            }
        }
        __syncthreads();

        // FMA loop: broadcast weights from smem, packed f32x2 accumulate
        #pragma unroll
        for (int i = 0; i < KC; ++i) {
            const unsigned long long xx = pack2(xv[i], xv[i]);
            const ulonglong2* wrow = reinterpret_cast<const ulonglong2*>(&wsh[i][n0]);
            ulonglong2 w01 = wrow[0];
            ulonglong2 w23 = wrow[1];
            acc0 = fma2(w01.x, xx, acc0);
            acc1 = fma2(w01.y, xx, acc1);
            acc2 = fma2(w23.x, xx, acc2);
            acc3 = fma2(w23.y, xx, acc3);
        }
        __syncthreads();
    }

    // write partials (deterministic reduction later)
    float* outp = (PHASE1 ? &g_hpart[0][0] : &g_opart[0][0])
                  + (size_t)blockIdx.y * (BATCH * NCOLS);
    float* dst = outp + lane * NCOLS + n_base + n0;
    unsigned long long a[4] = {acc0, acc1, acc2, acc3};
    #pragma unroll
    for (int j = 0; j < 4; ++j) {
        dst[2 * j]     = __uint_as_float((uint32_t)(a[j] & 0xffffffffu));
        dst[2 * j + 1] = __uint_as_float((uint32_t)(a[j] >> 32));
    }
}

// ---------------- SwiGLU: reduce gemm1 partials, write actT f32 ----------
__global__ void __launch_bounds__(THREADS) swiglu_kernel() {
    int idx = blockIdx.x * THREADS + threadIdx.x;   // over IDIM*BATCH
    int b = idx & 31;
    int i = idx >> 5;
    float hg = 0.f, hu = 0.f;
    #pragma unroll
    for (int s = 0; s < KSPLIT; ++s) {
        hg += g_hpart[s][b * NCOLS + i];
        hu += g_hpart[s][b * NCOLS + i + IDIM];
    }
    float sig = 1.0f / (1.0f + __expf(-hg));
    g_actT[idx] = hg * sig * hu;    // idx == i*32 + b  -> coalesced write
}

// ---------------- reduce gemm2 partials -> f32 output --------------------
__global__ void __launch_bounds__(THREADS) reduce_out_kernel(float* __restrict__ out) {
    int idx = blockIdx.x * THREADS + threadIdx.x;   // over BATCH*NCOLS
    float s = 0.f;
    #pragma unroll
    for (int sp = 0; sp < KSPLIT; ++sp)
        s += g_opart[sp][idx];
    // reference output is f16 then harness-promoted to f32: round to f16 grid
    out[idx] = __half2float(__float2half(s));
}

// ---------------- launch --------------------------------------------------
extern "C" void kernel_launch(void* const* d_in, const int* in_sizes, int n_in,
                              void* d_out, int out_size) {
    const float* x   = (const float*)d_in[0];  // [32][4096] f32 (promoted f16)
    const int*   gup = (const int*)  d_in[1];  // [512][4096] packed FP4
    const float* gus = (const float*)d_in[2];  // [32][4096] f32 scales
    const int*   dwn = (const int*)  d_in[3];  // [256][4096] packed FP4
    const float* dws = (const float*)d_in[4];  // [16][4096] f32 scales
    float* out = (float*)d_out;                // [32][4096] f32

    transpose_x_kernel<<<(HDIM * BATCH) / THREADS, THREADS>>>(x);

    gemm_dq_kernel<HDIM, true><<<dim3(NCOLS / NT, KSPLIT), THREADS>>>(gup, gus);

    swiglu_kernel<<<(IDIM * BATCH) / THREADS, THREADS>>>();

    gemm_dq_kernel<IDIM, false><<<dim3(NCOLS / NT, KSPLIT), THREADS>>>(dwn, dws);

    reduce_out_kernel<<<(BATCH * NCOLS) / THREADS, THREADS>>>(out);
}

// round 3
// speedup vs baseline: 1.2930x; 1.2930x over previous
#include <cuda_runtime.h>
#include <cuda_fp16.h>
#include <stdint.h>

// Problem constants (fixed by the dataset)
#define BATCH   32
#define HDIM    4096     // hidden dim (K of gemm1, N of gemm2)
#define IDIM    2048     // intermediate (K of gemm2)
#define NCOLS   4096     // N of both GEMMs (2*I for gemm1, H for gemm2)
#define GSZ     128      // quant group size

// Tiling
#define NT      128      // columns per block
#define KC      32       // K per chunk (one smem stage)
#define KSPLIT  16       // K-split factor (deterministic partials)
#define THREADS 256
// thread tile: 8 batch rows (as 4 f32x2 pairs) x 2 columns

// ---------------- scratch (__device__ globals; no allocation allowed) ----
__device__ float g_xT[HDIM * BATCH];              // x transposed, f32 [k][b]
__device__ float g_actT[IDIM * BATCH];            // SwiGLU act transposed [i][b]
__device__ float g_hpart[KSPLIT][BATCH * NCOLS];  // gemm1 partials
__device__ float g_opart[KSPLIT][BATCH * NCOLS];  // gemm2 partials

// ---------------- packed f32x2 helpers ----------------------------------
__device__ __forceinline__ unsigned long long pack2(float lo, float hi) {
    unsigned long long r;
    asm("mov.b64 %0, {%1, %2};" : "=l"(r) : "f"(lo), "f"(hi));
    return r;
}
__device__ __forceinline__ unsigned long long fma2(unsigned long long a,
                                                   unsigned long long b,
                                                   unsigned long long c) {
    unsigned long long d;
    asm("fma.rn.f32x2 %0, %1, %2, %3;" : "=l"(d) : "l"(a), "l"(b), "l"(c));
    return d;
}
__device__ __forceinline__ float lo32(unsigned long long v) {
    return __uint_as_float((uint32_t)(v & 0xffffffffu));
}
__device__ __forceinline__ float hi32(unsigned long long v) {
    return __uint_as_float((uint32_t)(v >> 32));
}

// FP4 E2M1 nibble -> f32, scaled by 2^-14 (caller folds 2^14 into scale).
// fp16 bit pattern (s<<15)|(eem<<9) == fp4_value * 2^-14 exactly.
__device__ __forceinline__ float fp4_raw(uint32_t nib) {
    uint32_t hb = ((nib & 8u) << 12) | ((nib & 7u) << 9);
    return __half2float(__ushort_as_half((unsigned short)hb));
}

// ---------------- kernel 0: x [B][H] f32 -> xT [H][B] f32 ----------------
__global__ void __launch_bounds__(THREADS) transpose_x_kernel(const float* __restrict__ x) {
    int idx = blockIdx.x * THREADS + threadIdx.x;   // over HDIM*BATCH
    int k = idx >> 5;
    int b = idx & 31;
    g_xT[idx] = x[b * HDIM + k];
}

// ---------------- fused dequant-GEMM (both phases) -----------------------
// Block tile: 32 batch x 128 cols. Thread tile: 8 batch x 2 cols.
// x pairs (adjacent batch rows) come straight from smem as 64-bit operands;
// w scalars are duplicated into f32x2 via pack2.
template <int KDIM, bool PHASE1>
__global__ void __launch_bounds__(THREADS) gemm_dq_kernel(
    const int*   __restrict__ packed,   // [KDIM/8][NCOLS]
    const float* __restrict__ scales)   // [KDIM/GSZ][NCOLS]
{
    __shared__ __align__(16) float xsh[KC * BATCH];   // 4 KB, [k][b]
    __shared__ __align__(16) float wsh[KC][NT];       // 16 KB

    const float* __restrict__ xT = PHASE1 ? g_xT : g_actT;

    const int tid  = threadIdx.x;
    const int mg   = tid >> 6;          // 0..3 : batch group of 8 rows
    const int ng   = tid & 63;          // 0..63: column group of 2 cols
    const int n_base  = blockIdx.x * NT;
    const int kspan   = KDIM / KSPLIT;
    const int k_begin = blockIdx.y * kspan;
    const int nchunks = kspan / KC;

    // dequant assignment: 4 word-rows x 128 cols = 512 words/chunk, 2/thread
    const int dq_col = tid & 127;                 // 0..127
    const int dq_r0  = (tid >> 7) * 2;            // rows {0,1} or {2,3}
    const int dq_n   = n_base + dq_col;

    // prefetch registers
    uint32_t wword[2];
    float    sf;
    float4   xv;

    // ---- prefetch chunk 0 ----
    {
        const int k0 = k_begin;
        const int k8 = (k0 >> 3) + dq_r0;
        wword[0] = (uint32_t)packed[k8 * NCOLS + dq_n];
        wword[1] = (uint32_t)packed[(k8 + 1) * NCOLS + dq_n];
        sf = scales[(k8 >> 4) * NCOLS + dq_n] * 16384.0f;
        xv = reinterpret_cast<const float4*>(xT)[k0 * (BATCH / 4) + tid];
    }

    unsigned long long acc[4][2];
    #pragma unroll
    for (int m = 0; m < 4; ++m) { acc[m][0] = 0ull; acc[m][1] = 0ull; }

    for (int c = 0; c < nchunks; ++c) {
        if (c) __syncthreads();   // prior compute done before smem overwrite

        // ---- store phase: x staging + cooperative dequant ----
        reinterpret_cast<float4*>(xsh)[tid] = xv;
        #pragma unroll
        for (int r = 0; r < 2; ++r) {
            const uint32_t word = wword[r];
            #pragma unroll
            for (int j = 0; j < 8; ++j) {
                uint32_t nib = (word >> (4 * j)) & 0xFu;
                wsh[(dq_r0 + r) * 8 + j][dq_col] = fp4_raw(nib) * sf;
            }
        }
        __syncthreads();

        // ---- prefetch chunk c+1 (LDG in flight under compute) ----
        if (c + 1 < nchunks) {
            const int k0 = k_begin + (c + 1) * KC;
            const int k8 = (k0 >> 3) + dq_r0;
            wword[0] = (uint32_t)packed[k8 * NCOLS + dq_n];
            wword[1] = (uint32_t)packed[(k8 + 1) * NCOLS + dq_n];
            sf = scales[(k8 >> 4) * NCOLS + dq_n] * 16384.0f;
            xv = reinterpret_cast<const float4*>(xT)[k0 * (BATCH / 4) + tid];
        }

        // ---- compute: 32 k-steps, 16 MACs each ----
        const ulonglong2* xshu = reinterpret_cast<const ulonglong2*>(xsh);
        #pragma unroll
        for (int k = 0; k < KC; ++k) {
            // 8 batch rows for this thread, as 4 packed f32x2 pairs
            ulonglong2 xa = xshu[k * (BATCH / 4) + mg * 2];       // b pairs 0,1
            ulonglong2 xb = xshu[k * (BATCH / 4) + mg * 2 + 1];   // b pairs 2,3
            float2 wv = *reinterpret_cast<const float2*>(&wsh[k][ng * 2]);
            unsigned long long w0 = pack2(wv.x, wv.x);
            unsigned long long w1 = pack2(wv.y, wv.y);
            acc[0][0] = fma2(xa.x, w0, acc[0][0]);
            acc[0][1] = fma2(xa.x, w1, acc[0][1]);
            acc[1][0] = fma2(xa.y, w0, acc[1][0]);
            acc[1][1] = fma2(xa.y, w1, acc[1][1]);
            acc[2][0] = fma2(xb.x, w0, acc[2][0]);
            acc[2][1] = fma2(xb.x, w1, acc[2][1]);
            acc[3][0] = fma2(xb.y, w0, acc[3][0]);
            acc[3][1] = fma2(xb.y, w1, acc[3][1]);
        }
    }

    // ---- write partials (deterministic reduction later) ----
    float* outp = (PHASE1 ? &g_hpart[0][0] : &g_opart[0][0])
                  + (size_t)blockIdx.y * (BATCH * NCOLS);
    const int col = n_base + ng * 2;
    #pragma unroll
    for (int mp = 0; mp < 4; ++mp) {
        const int b0 = mg * 8 + mp * 2;
        outp[(b0)     * NCOLS + col]     = lo32(acc[mp][0]);
        outp[(b0 + 1) * NCOLS + col]     = hi32(acc[mp][0]);
        outp[(b0)     * NCOLS + col + 1] = lo32(acc[mp][1]);
        outp[(b0 + 1) * NCOLS + col + 1] = hi32(acc[mp][1]);
    }
}

// ---------------- SwiGLU: reduce gemm1 partials, write actT f32 ----------
__global__ void __launch_bounds__(THREADS) swiglu_kernel() {
    int idx = blockIdx.x * THREADS + threadIdx.x;   // over IDIM*BATCH
    int b = idx & 31;
    int i = idx >> 5;
    float hg = 0.f, hu = 0.f;
    #pragma unroll
    for (int s = 0; s < KSPLIT; ++s) {
        hg += g_hpart[s][b * NCOLS + i];
        hu += g_hpart[s][b * NCOLS + i + IDIM];
    }
    float sig = 1.0f / (1.0f + __expf(-hg));
    g_actT[idx] = hg * sig * hu;    // idx == i*32 + b  -> coalesced write
}

// ---------------- reduce gemm2 partials -> f32 output --------------------
__global__ void __launch_bounds__(THREADS) reduce_out_kernel(float* __restrict__ out) {
    int idx = blockIdx.x * THREADS + threadIdx.x;   // over BATCH*NCOLS
    float s = 0.f;
    #pragma unroll
    for (int sp = 0; sp < KSPLIT; ++sp)
        s += g_opart[sp][idx];
    // reference output is f16 then harness-promoted to f32: round to f16 grid
    out[idx] = __half2float(__float2half(s));
}

// ---------------- launch --------------------------------------------------
extern "C" void kernel_launch(void* const* d_in, const int* in_sizes, int n_in,
                              void* d_out, int out_size) {
    const float* x   = (const float*)d_in[0];  // [32][4096] f32 (promoted f16)
    const int*   gup = (const int*)  d_in[1];  // [512][4096] packed FP4
    const float* gus = (const float*)d_in[2];  // [32][4096] f32 scales
    const int*   dwn = (const int*)  d_in[3];  // [256][4096] packed FP4
    const float* dws = (const float*)d_in[4];  // [16][4096] f32 scales
    float* out = (float*)d_out;                // [32][4096] f32

    transpose_x_kernel<<<(HDIM * BATCH) / THREADS, THREADS>>>(x);

    gemm_dq_kernel<HDIM, true><<<dim3(NCOLS / NT, KSPLIT), THREADS>>>(gup, gus);

    swiglu_kernel<<<(IDIM * BATCH) / THREADS, THREADS>>>();

    gemm_dq_kernel<IDIM, false><<<dim3(NCOLS / NT, KSPLIT), THREADS>>>(dwn, dws);

    reduce_out_kernel<<<(BATCH * NCOLS) / THREADS, THREADS>>>(out);
}

// round 5
// speedup vs baseline: 2.7007x; 2.0887x over previous
#include <cuda_runtime.h>
#include <cuda_fp16.h>
#include <stdint.h>

#define BATCH   32
#define HDIM    4096
#define IDIM    2048
#define NCOLS   4096
#define GSZ     128

#define KSPLIT  16
#define MTILE   128      // weight columns per block
#define KCHUNK  64       // K per smem stage

// ---------------- scratch ------------------------------------------------
__device__ __align__(16) __half g_xh[BATCH * HDIM];     // x fp16 [b][k]
__device__ __align__(16) __half g_acth[BATCH * IDIM];   // act fp16 [b][i]
__device__ float g_hpart[KSPLIT][NCOLS * BATCH];        // gemm1 partials [s][n][b]
__device__ float g_opart[KSPLIT][NCOLS * BATCH];        // gemm2 partials [s][n][b]

// ---------------- helpers -------------------------------------------------
__device__ __forceinline__ uint32_t smem_u32(const void* p) {
    uint32_t a;
    asm("{ .reg .u64 t; cvta.to.shared.u64 t, %1; cvt.u32.u64 %0, t; }"
        : "=r"(a) : "l"(p));
    return a;
}

__device__ __forceinline__ void ldsm_x4(uint32_t& r0, uint32_t& r1,
                                        uint32_t& r2, uint32_t& r3, uint32_t addr) {
    asm volatile("ldmatrix.sync.aligned.m8n8.x4.shared.b16 {%0,%1,%2,%3}, [%4];"
                 : "=r"(r0), "=r"(r1), "=r"(r2), "=r"(r3) : "r"(addr));
}

__device__ __forceinline__ void mma_16816(float* c, const uint32_t* a, const uint32_t* b) {
    asm volatile(
        "mma.sync.aligned.m16n8k16.row.col.f32.f16.f16.f32 "
        "{%0,%1,%2,%3}, {%4,%5,%6,%7}, {%8,%9}, {%0,%1,%2,%3};"
        : "+f"(c[0]), "+f"(c[1]), "+f"(c[2]), "+f"(c[3])
        : "r"(a[0]), "r"(a[1]), "r"(a[2]), "r"(a[3]), "r"(b[0]), "r"(b[1]));
}

// FP4 word (8 nibbles) -> 4 x fp16x2 (k pairs 01,23,45,67), scaled.
// sf2 = half2(scale * 2^14). Byte-splat via PRMT; fp16 pattern (s<<15)|(eem<<9)
// equals fp4_value * 2^-14 exactly (incl. subnormals); mul.f16x2 keeps denormals.
__device__ __forceinline__ void dq_word(uint32_t w, uint32_t sf2, uint32_t out[4]) {
    #pragma unroll
    for (int b = 0; b < 4; ++b) {
        uint32_t t;
        asm("prmt.b32 %0, %1, %1, %2;" : "=r"(t) : "r"(w), "r"(b * 0x1111));
        uint32_t h = ((t << 9) & 0x00000E00u) | ((t << 4) & 0x00008000u)
                   | ((t << 5) & 0x0E000000u) | (t & 0x80000000u);
        uint32_t r;
        asm("mul.f16x2 %0, %1, %2;" : "=r"(r) : "r"(h), "r"(sf2));
        out[b] = r;
    }
}

// ---------------- prep: x f32 -> fp16 ------------------------------------
__global__ void __launch_bounds__(512) prep_x_kernel(const float* __restrict__ x) {
    int idx = blockIdx.x * 512 + threadIdx.x;
    g_xh[idx] = __float2half_rn(x[idx]);   // exact: x was fp16 originally
}

// ---------------- HMMA dequant-GEMM --------------------------------------
// partial[n][b] += sum_k dequant(W[k][n]) * act[b][k]
template <int KDIM, bool PHASE1>
__global__ void __launch_bounds__(256) gemm_mma_kernel(
    const int*   __restrict__ packed,   // [KDIM/8][NCOLS]
    const float* __restrict__ scales)   // [KDIM/GSZ][NCOLS]
{
    __shared__ __align__(16) __half Ash[MTILE * KCHUNK];   // 16 KB
    __shared__ __align__(16) __half Bsh[BATCH * KCHUNK];   //  4 KB

    const int tid  = threadIdx.x;
    const int wid  = tid >> 5;
    const int lane = tid & 31;

    const __half* __restrict__ Bsrc = PHASE1 ? g_xh : g_acth;

    const int n_base  = blockIdx.x * MTILE;
    const int kspan   = KDIM / KSPLIT;
    const int k_begin = blockIdx.y * kspan;
    const int nchunks = kspan / KCHUNK;

    // dequant mapping: 2 threads per A row, 4 packed words each
    const int arow = tid & 127;
    const int jh   = tid >> 7;                      // 0/1
    const int ar7s = arow & 7;
    const int n_glob = n_base + arow;
    const uint32_t* pk = (const uint32_t*)packed
                       + (size_t)(k_begin >> 3) * NCOLS + n_glob;

    // B staging: one uint4 per thread (32 rows x 8 chunks)
    const int brow = tid >> 3;
    const int bcx  = tid & 7;
    const __half* bgp = Bsrc + (size_t)brow * KDIM + k_begin + bcx * 8;
    __half* bsp = Bsh + brow * KCHUNK + ((bcx ^ (brow & 7)) * 8);

    // ---- prefetch chunk 0 ----
    uint32_t wreg[4];
    float    sc;
    uint4    xv;
    #pragma unroll
    for (int i = 0; i < 4; ++i)
        wreg[i] = pk[(size_t)(jh * 4 + i) * NCOLS];
    sc = scales[(size_t)(k_begin >> 7) * NCOLS + n_glob];
    xv = *(const uint4*)bgp;

    float acc[4][4] = {};

    // ldmatrix lane address precompute
    const uint32_t Abase = smem_u32(Ash), Bbase = smem_u32(Bsh);
    const int sub = lane >> 3, l7 = lane & 7;
    const int m0  = wid * 16;
    const int ar  = m0 + l7 + (sub & 1) * 8;   // A lane row
    const int ar7 = ar & 7;
    const uint32_t a_rowbase = Abase + (uint32_t)ar * (KCHUNK * 2);
    const int acx_off = (sub >> 1);            // k-chunk sub-offset for A
    const int bn0 = l7 + (sub >> 1) * 8;       // B lane row (n-tile pair base)
    const int bcx_off = (sub & 1);

    for (int c = 0; c < nchunks; ++c) {
        if (c) __syncthreads();   // prior compute done before smem overwrite

        // ---- store B tile ----
        *(uint4*)bsp = xv;

        // ---- dequant + store A tile ----
        {
            __half hs = __float2half_rn(sc * 16384.0f);   // exact pow2 fold
            uint32_t sf2 = (uint32_t)__half_as_ushort(hs) * 0x00010001u;
            #pragma unroll
            for (int i = 0; i < 4; ++i) {
                const int j = jh * 4 + i;
                uint32_t o[4];
                dq_word(wreg[i], sf2, o);
                *(uint4*)(Ash + arow * KCHUNK + ((j ^ ar7s) * 8)) =
                    make_uint4(o[0], o[1], o[2], o[3]);
            }
        }
        __syncthreads();

        // ---- prefetch chunk c+1 (LDG under compute) ----
        if (c + 1 < nchunks) {
            #pragma unroll
            for (int i = 0; i < 4; ++i)
                wreg[i] = pk[(size_t)((c + 1) * 8 + jh * 4 + i) * NCOLS];
            sc = scales[(size_t)((k_begin + (c + 1) * KCHUNK) >> 7) * NCOLS + n_glob];
            xv = *(const uint4*)(bgp + (c + 1) * KCHUNK);
        }

        // ---- compute: 4 k16 steps, 4 MMAs each ----
        #pragma unroll
        for (int ks = 0; ks < 4; ++ks) {
            uint32_t a[4], b0[4], b1[4];
            const int acx = ks * 2 + acx_off;
            ldsm_x4(a[0], a[1], a[2], a[3],
                    a_rowbase + (uint32_t)((acx ^ ar7) << 4));
            const int bcxs = ks * 2 + bcx_off;
            {
                const int n = bn0;
                ldsm_x4(b0[0], b0[1], b0[2], b0[3],
                        Bbase + (uint32_t)(n * (KCHUNK * 2))
                              + (uint32_t)((bcxs ^ (n & 7)) << 4));
            }
            {
                const int n = bn0 + 16;
                ldsm_x4(b1[0], b1[1], b1[2], b1[3],
                        Bbase + (uint32_t)(n * (KCHUNK * 2))
                              + (uint32_t)((bcxs ^ (n & 7)) << 4));
            }
            mma_16816(acc[0], a, &b0[0]);
            mma_16816(acc[1], a, &b0[2]);
            mma_16816(acc[2], a, &b1[0]);
            mma_16816(acc[3], a, &b1[2]);
        }
    }

    // ---- epilogue: D fragment -> partials [n][b], float2 stores ----
    float* outp = (PHASE1 ? &g_hpart[0][0] : &g_opart[0][0])
                  + (size_t)blockIdx.y * (NCOLS * BATCH);
    const int gq = lane >> 2, tq = lane & 3;
    const int nrow0 = n_base + m0 + gq;
    #pragma unroll
    for (int t = 0; t < 4; ++t) {
        const int bcol = t * 8 + tq * 2;
        *(float2*)&outp[(size_t)nrow0 * BATCH + bcol]       = make_float2(acc[t][0], acc[t][1]);
        *(float2*)&outp[(size_t)(nrow0 + 8) * BATCH + bcol] = make_float2(acc[t][2], acc[t][3]);
    }
}

// ---------------- SwiGLU: reduce gemm1 partials -> act fp16 [b][i] -------
__global__ void __launch_bounds__(256) swiglu_kernel() {
    __shared__ float s_act[64][33];
    const int i0 = blockIdx.x * 64;
    const int b  = threadIdx.x & 31;
    const int il = threadIdx.x >> 5;         // 0..7
    #pragma unroll
    for (int ii = 0; ii < 8; ++ii) {
        const int ilocal = il * 8 + ii;
        const size_t ng = (size_t)(i0 + ilocal) * BATCH + b;
        float hg = 0.f, hu = 0.f;
        #pragma unroll
        for (int s = 0; s < KSPLIT; ++s) {
            hg += g_hpart[s][ng];
            hu += g_hpart[s][ng + (size_t)IDIM * BATCH];
        }
        const float sig = 1.0f / (1.0f + __expf(-hg));
        s_act[ilocal][b] = hg * sig * hu;
    }
    __syncthreads();
    const int i2 = threadIdx.x & 63;
    const int b2 = threadIdx.x >> 6;         // 0..3
    #pragma unroll
    for (int bb = 0; bb < 8; ++bb) {
        const int b3 = b2 * 8 + bb;
        g_acth[(size_t)b3 * IDIM + i0 + i2] = __float2half_rn(s_act[i2][b3]);
    }
}

// ---------------- reduce gemm2 partials [n][b] -> out [b][n] f32 ---------
__global__ void __launch_bounds__(256) reduce_out_kernel(float* __restrict__ out) {
    __shared__ float s_o[64][33];
    const int h0 = blockIdx.x * 64;
    const int b  = threadIdx.x & 31;
    const int hl = threadIdx.x >> 5;
    #pragma unroll
    for (int hh = 0; hh < 8; ++hh) {
        const int hlocal = hl * 8 + hh;
        const size_t ng = (size_t)(h0 + hlocal) * BATCH + b;
        float s = 0.f;
        #pragma unroll
        for (int sp = 0; sp < KSPLIT; ++sp)
            s += g_opart[sp][ng];
        s_o[hlocal][b] = s;
    }
    __syncthreads();
    const int h2 = threadIdx.x & 63;
    const int b2 = threadIdx.x >> 6;
    #pragma unroll
    for (int bb = 0; bb < 8; ++bb) {
        const int b3 = b2 * 8 + bb;
        // reference output is f16 (harness-promoted): round to f16 grid
        out[(size_t)b3 * NCOLS + h0 + h2] =
            __half2float(__float2half_rn(s_o[h2][b3]));
    }
}

// ---------------- launch --------------------------------------------------
extern "C" void kernel_launch(void* const* d_in, const int* in_sizes, int n_in,
                              void* d_out, int out_size) {
    const float* x   = (const float*)d_in[0];
    const int*   gup = (const int*)  d_in[1];
    const float* gus = (const float*)d_in[2];
    const int*   dwn = (const int*)  d_in[3];
    const float* dws = (const float*)d_in[4];
    float* out = (float*)d_out;

    prep_x_kernel<<<(BATCH * HDIM) / 512, 512>>>(x);

    gemm_mma_kernel<HDIM, true><<<dim3(NCOLS / MTILE, KSPLIT), 256>>>(gup, gus);

    swiglu_kernel<<<IDIM / 64, 256>>>();

    gemm_mma_kernel<IDIM, false><<<dim3(NCOLS / MTILE, KSPLIT), 256>>>(dwn, dws);

    reduce_out_kernel<<<NCOLS / 64, 256>>>(out);
}

// round 6
// speedup vs baseline: 3.1064x; 1.1502x over previous
#include <cuda_runtime.h>
#include <cuda_fp16.h>
#include <stdint.h>

#define BATCH   32
#define HDIM    4096
#define IDIM    2048
#define NCOLS   4096
#define GSZ     128

#define KSPLIT  8
#define MTILE   64       // weight columns per block
#define KCHUNK  64       // K per smem stage

// ---------------- scratch ------------------------------------------------
__device__ __align__(16) __half g_acth[BATCH * IDIM];   // act fp16 [b][i]
__device__ float g_hpart[KSPLIT][NCOLS * BATCH];        // gemm1 partials [s][n][b]
__device__ float g_opart[KSPLIT][NCOLS * BATCH];        // gemm2 partials [s][n][b]

// ---------------- helpers -------------------------------------------------
__device__ __forceinline__ uint32_t smem_u32(const void* p) {
    uint32_t a;
    asm("{ .reg .u64 t; cvta.to.shared.u64 t, %1; cvt.u32.u64 %0, t; }"
        : "=r"(a) : "l"(p));
    return a;
}
__device__ __forceinline__ void ldsm_x4(uint32_t& r0, uint32_t& r1,
                                        uint32_t& r2, uint32_t& r3, uint32_t addr) {
    asm volatile("ldmatrix.sync.aligned.m8n8.x4.shared.b16 {%0,%1,%2,%3}, [%4];"
                 : "=r"(r0), "=r"(r1), "=r"(r2), "=r"(r3) : "r"(addr));
}
__device__ __forceinline__ void mma_16816(float* c, const uint32_t* a, const uint32_t* b) {
    asm volatile(
        "mma.sync.aligned.m16n8k16.row.col.f32.f16.f16.f32 "
        "{%0,%1,%2,%3}, {%4,%5,%6,%7}, {%8,%9}, {%0,%1,%2,%3};"
        : "+f"(c[0]), "+f"(c[1]), "+f"(c[2]), "+f"(c[3])
        : "r"(a[0]), "r"(a[1]), "r"(a[2]), "r"(a[3]), "r"(b[0]), "r"(b[1]));
}

// FP4 word (8 nibbles) -> 4 x fp16x2 (k pairs 01,23,45,67), scaled.
// sf2 = half2(scale * 2^14). fp16 pattern (s<<15)|(eem<<9) == fp4 * 2^-14.
__device__ __forceinline__ void dq_word(uint32_t w, uint32_t sf2, uint32_t out[4]) {
    #pragma unroll
    for (int b = 0; b < 4; ++b) {
        uint32_t t;
        asm("prmt.b32 %0, %1, %1, %2;" : "=r"(t) : "r"(w), "r"(b * 0x1111));
        uint32_t h = ((t << 9) & 0x00000E00u) | ((t << 4) & 0x00008000u)
                   | ((t << 5) & 0x0E000000u) | (t & 0x80000000u);
        uint32_t r;
        asm("mul.f16x2 %0, %1, %2;" : "=r"(r) : "r"(h), "r"(sf2));
        out[b] = r;
    }
}

// ---------------- HMMA dequant-GEMM --------------------------------------
// partial[n][b] += sum_k dequant(W[k][n]) * act[b][k]
// PHASE1: B source is f32 x (converted inline); PHASE2: fp16 act.
template <int KDIM, bool PHASE1>
__global__ void __launch_bounds__(256) gemm_mma_kernel(
    const int*   __restrict__ packed,   // [KDIM/8][NCOLS]
    const float* __restrict__ scales,   // [KDIM/GSZ][NCOLS]
    const void*  __restrict__ bsrc)     // PHASE1: f32 x[b][k]; PHASE2: unused
{
    constexpr int NCH = (KDIM / KSPLIT) / KCHUNK;   // 8 (gemm1) / 4 (gemm2)

    __shared__ __align__(16) __half Ash[2][MTILE * KCHUNK];   // 2 x 8 KB
    __shared__ __align__(16) __half Bsh[2][BATCH * KCHUNK];   // 2 x 4 KB

    const int tid  = threadIdx.x;
    const int wid  = tid >> 5;
    const int lane = tid & 31;

    const int n_base  = blockIdx.x * MTILE;
    const int k_begin = blockIdx.y * (KDIM / KSPLIT);

    // dequant mapping: thread -> (col arow, word pair j0=2*jp)
    const int arow = tid & 63;
    const int jp   = tid >> 6;               // 0..3
    const int j0   = jp * 2;
    const int ar7s = arow & 7;
    const int n_glob = n_base + arow;
    const uint32_t* pk = (const uint32_t*)packed
                       + (size_t)(k_begin >> 3) * NCOLS + n_glob;
    const float* scp = scales + n_glob;

    // B staging: 32 rows x 8 chunks of 16B, one per thread
    const int brow = tid >> 3;
    const int bcx  = tid & 7;
    const size_t boff0 = (size_t)brow * KDIM + k_begin + bcx * 8;   // in elements
    __half* bsp0 = &Bsh[0][brow * KCHUNK + ((bcx ^ (brow & 7)) * 8)];
    __half* bsp1 = &Bsh[1][brow * KCHUNK + ((bcx ^ (brow & 7)) * 8)];

    const float*  xf = (const float*)bsrc;
    const __half* xh = PHASE1 ? (const __half*)nullptr : g_acth;

    // slot registers (2-chunk-deep prefetch)
    uint32_t w0a, w1a, w0b, w1b;
    float    sca, scb;
    uint4    xva, xvb;

    auto loadW = [&](int c, uint32_t& w0, uint32_t& w1, float& sc) {
        w0 = pk[(size_t)(c * 8 + j0)     * NCOLS];
        w1 = pk[(size_t)(c * 8 + j0 + 1) * NCOLS];
        sc = scp[(size_t)((k_begin + c * KCHUNK) >> 7) * NCOLS];
    };
    auto loadB = [&](int c, uint4& xv) {
        const size_t off = boff0 + (size_t)c * KCHUNK;
        if (PHASE1) {
            float4 a = *(const float4*)(xf + off);
            float4 b = *(const float4*)(xf + off + 4);
            __half2 h0 = __float22half2_rn(make_float2(a.x, a.y));
            __half2 h1 = __float22half2_rn(make_float2(a.z, a.w));
            __half2 h2 = __float22half2_rn(make_float2(b.x, b.y));
            __half2 h3 = __float22half2_rn(make_float2(b.z, b.w));
            xv = make_uint4(*(uint32_t*)&h0, *(uint32_t*)&h1,
                            *(uint32_t*)&h2, *(uint32_t*)&h3);
        } else {
            xv = *(const uint4*)(xh + off);
        }
    };

    // ---- prefetch chunks 0,1 ----
    loadW(0, w0a, w1a, sca); loadB(0, xva);
    loadW(1, w0b, w1b, scb); loadB(1, xvb);

    float acc[2][4] = {};

    // MMA lane addressing (constant per thread)
    const uint32_t Abase0 = smem_u32(&Ash[0][0]);
    const uint32_t Bbase0 = smem_u32(&Bsh[0][0]);
    const int sub = lane >> 3, l7 = lane & 7;
    const int mrow = (wid & 3) * 16;
    const int nh   = wid >> 2;                  // 0/1: batch half
    const int ar   = mrow + l7 + (sub & 1) * 8;
    const int ar7  = ar & 7;
    const uint32_t a_row = (uint32_t)ar * (KCHUNK * 2);
    const int acx_off = sub >> 1;
    const int bn  = nh * 16 + l7 + (sub >> 1) * 8;
    const int bn7 = bn & 7;
    const uint32_t b_row = (uint32_t)bn * (KCHUNK * 2);
    const int bcx_off = sub & 1;

    auto dq_store = [&](int buf, uint32_t w0, uint32_t w1, float sc, uint4 xv) {
        *(uint4*)(buf ? bsp1 : bsp0) = xv;
        __half hs = __float2half_rn(sc * 16384.0f);   // exact pow2 fold
        uint32_t sf2 = (uint32_t)__half_as_ushort(hs) * 0x00010001u;
        uint32_t o[4];
        dq_word(w0, sf2, o);
        *(uint4*)(&Ash[buf][arow * KCHUNK + ((j0 ^ ar7s) * 8)]) =
            make_uint4(o[0], o[1], o[2], o[3]);
        dq_word(w1, sf2, o);
        *(uint4*)(&Ash[buf][arow * KCHUNK + (((j0 + 1) ^ ar7s) * 8)]) =
            make_uint4(o[0], o[1], o[2], o[3]);
    };
    auto compute = [&](int buf) {
        const uint32_t Ab = Abase0 + (uint32_t)buf * (MTILE * KCHUNK * 2);
        const uint32_t Bb = Bbase0 + (uint32_t)buf * (BATCH * KCHUNK * 2);
        #pragma unroll
        for (int ks = 0; ks < 4; ++ks) {
            uint32_t a[4], b[4];
            ldsm_x4(a[0], a[1], a[2], a[3],
                    Ab + a_row + (uint32_t)(((ks * 2 + acx_off) ^ ar7) << 4));
            ldsm_x4(b[0], b[1], b[2], b[3],
                    Bb + b_row + (uint32_t)(((ks * 2 + bcx_off) ^ bn7) << 4));
            mma_16816(acc[0], a, &b[0]);
            mma_16816(acc[1], a, &b[2]);
        }
    };

    #pragma unroll
    for (int cc = 0; cc < NCH; cc += 2) {
        // even chunk -> buffer 0 / slot A
        dq_store(0, w0a, w1a, sca, xva);
        if (cc + 2 < NCH) { loadW(cc + 2, w0a, w1a, sca); loadB(cc + 2, xva); }
        __syncthreads();
        compute(0);
        // odd chunk -> buffer 1 / slot B
        dq_store(1, w0b, w1b, scb, xvb);
        if (cc + 3 < NCH) { loadW(cc + 3, w0b, w1b, scb); loadB(cc + 3, xvb); }
        __syncthreads();
        compute(1);
    }

    // ---- epilogue: D fragments -> partials [n][b] ----
    float* outp = (PHASE1 ? &g_hpart[0][0] : &g_opart[0][0])
                  + (size_t)blockIdx.y * (NCOLS * BATCH);
    const int gq = lane >> 2, tq = lane & 3;
    const int nrow0 = n_base + mrow + gq;
    #pragma unroll
    for (int t = 0; t < 2; ++t) {
        const int bcol = nh * 16 + t * 8 + tq * 2;
        *(float2*)&outp[(size_t)nrow0 * BATCH + bcol]       = make_float2(acc[t][0], acc[t][1]);
        *(float2*)&outp[(size_t)(nrow0 + 8) * BATCH + bcol] = make_float2(acc[t][2], acc[t][3]);
    }
}

// ---------------- SwiGLU: reduce gemm1 partials -> act fp16 [b][i] -------
__global__ void __launch_bounds__(256) swiglu_kernel() {
    __shared__ float s_act[64][33];
    const int i0 = blockIdx.x * 64;
    const int b  = threadIdx.x & 31;
    const int il = threadIdx.x >> 5;
    #pragma unroll
    for (int ii = 0; ii < 8; ++ii) {
        const int ilocal = il * 8 + ii;
        const size_t ng = (size_t)(i0 + ilocal) * BATCH + b;
        float hg = 0.f, hu = 0.f;
        #pragma unroll
        for (int s = 0; s < KSPLIT; ++s) {
            hg += g_hpart[s][ng];
            hu += g_hpart[s][ng + (size_t)IDIM * BATCH];
        }
        const float sig = 1.0f / (1.0f + __expf(-hg));
        s_act[ilocal][b] = hg * sig * hu;
    }
    __syncthreads();
    const int i2 = threadIdx.x & 63;
    const int b2 = threadIdx.x >> 6;
    #pragma unroll
    for (int bb = 0; bb < 8; ++bb) {
        const int b3 = b2 * 8 + bb;
        g_acth[(size_t)b3 * IDIM + i0 + i2] = __float2half_rn(s_act[i2][b3]);
    }
}

// ---------------- reduce gemm2 partials [n][b] -> out [b][n] f32 ---------
__global__ void __launch_bounds__(256) reduce_out_kernel(float* __restrict__ out) {
    __shared__ float s_o[64][33];
    const int h0 = blockIdx.x * 64;
    const int b  = threadIdx.x & 31;
    const int hl = threadIdx.x >> 5;
    #pragma unroll
    for (int hh = 0; hh < 8; ++hh) {
        const int hlocal = hl * 8 + hh;
        const size_t ng = (size_t)(h0 + hlocal) * BATCH + b;
        float s = 0.f;
        #pragma unroll
        for (int sp = 0; sp < KSPLIT; ++sp)
            s += g_opart[sp][ng];
        s_o[hlocal][b] = s;
    }
    __syncthreads();
    const int h2 = threadIdx.x & 63;
    const int b2 = threadIdx.x >> 6;
    #pragma unroll
    for (int bb = 0; bb < 8; ++bb) {
        const int b3 = b2 * 8 + bb;
        out[(size_t)b3 * NCOLS + h0 + h2] =
            __half2float(__float2half_rn(s_o[h2][b3]));   // f16 grid like ref
    }
}

// ---------------- launch --------------------------------------------------
extern "C" void kernel_launch(void* const* d_in, const int* in_sizes, int n_in,
                              void* d_out, int out_size) {
    const float* x   = (const float*)d_in[0];
    const int*   gup = (const int*)  d_in[1];
    const float* gus = (const float*)d_in[2];
    const int*   dwn = (const int*)  d_in[3];
    const float* dws = (const float*)d_in[4];
    float* out = (float*)d_out;

    gemm_mma_kernel<HDIM, true><<<dim3(NCOLS / MTILE, KSPLIT), 256>>>(gup, gus, x);

    swiglu_kernel<<<IDIM / 64, 256>>>();

    gemm_mma_kernel<IDIM, false><<<dim3(NCOLS / MTILE, KSPLIT), 256>>>(dwn, dws, nullptr);

    reduce_out_kernel<<<NCOLS / 64, 256>>>(out);
}

// round 7
// speedup vs baseline: 3.5815x; 1.1530x over previous
#include <cuda_runtime.h>
#include <cuda_fp16.h>
#include <stdint.h>

#define BATCH   32
#define HDIM    4096
#define IDIM    2048
#define NCOLS   4096
#define GSZ     128

#define KSPLIT  8
#define MTILE   64       // weight columns per block
#define KCHUNK  64       // K per smem stage

// ---------------- scratch ------------------------------------------------
__device__ __align__(16) __half g_acth[BATCH * IDIM];   // act fp16 [b][i]
__device__ float g_hpart[KSPLIT][NCOLS * BATCH];        // gemm1 partials [s][n][b]
__device__ float g_opart[KSPLIT][NCOLS * BATCH];        // gemm2 partials [s][n][b]

// ---------------- helpers -------------------------------------------------
__device__ __forceinline__ uint32_t smem_u32(const void* p) {
    uint32_t a;
    asm("{ .reg .u64 t; cvta.to.shared.u64 t, %1; cvt.u32.u64 %0, t; }"
        : "=r"(a) : "l"(p));
    return a;
}
__device__ __forceinline__ void ldsm_x4(uint32_t& r0, uint32_t& r1,
                                        uint32_t& r2, uint32_t& r3, uint32_t addr) {
    asm volatile("ldmatrix.sync.aligned.m8n8.x4.shared.b16 {%0,%1,%2,%3}, [%4];"
                 : "=r"(r0), "=r"(r1), "=r"(r2), "=r"(r3) : "r"(addr));
}
__device__ __forceinline__ void mma_16816(float* c, const uint32_t* a, const uint32_t* b) {
    asm volatile(
        "mma.sync.aligned.m16n8k16.row.col.f32.f16.f16.f32 "
        "{%0,%1,%2,%3}, {%4,%5,%6,%7}, {%8,%9}, {%0,%1,%2,%3};"
        : "+f"(c[0]), "+f"(c[1]), "+f"(c[2]), "+f"(c[3])
        : "r"(a[0]), "r"(a[1]), "r"(a[2]), "r"(a[3]), "r"(b[0]), "r"(b[1]));
}

// FP4 word (8 nibbles) -> 4 x fp16x2 (k pairs 01,23,45,67), scaled.
// sf2 = half2(scale * 2^14). fp16 pattern (s<<15)|(eem<<9) == fp4 * 2^-14.
__device__ __forceinline__ void dq_word(uint32_t w, uint32_t sf2, uint32_t out[4]) {
    #pragma unroll
    for (int b = 0; b < 4; ++b) {
        uint32_t t;
        asm("prmt.b32 %0, %1, %1, %2;" : "=r"(t) : "r"(w), "r"(b * 0x1111));
        uint32_t h = ((t << 9) & 0x00000E00u) | ((t << 4) & 0x00008000u)
                   | ((t << 5) & 0x0E000000u) | (t & 0x80000000u);
        uint32_t r;
        asm("mul.f16x2 %0, %1, %2;" : "=r"(r) : "r"(h), "r"(sf2));
        out[b] = r;
    }
}

// ---------------- HMMA dequant-GEMM --------------------------------------
// partial[n][b] += sum_k dequant(W[k][n]) * act[b][k]
// PHASE1: B source is f32 x (converted inline); PHASE2: fp16 act.
template <int KDIM, bool PHASE1>
__global__ void __launch_bounds__(256) gemm_mma_kernel(
    const int*   __restrict__ packed,   // [KDIM/8][NCOLS]
    const float* __restrict__ scales,   // [KDIM/GSZ][NCOLS]
    const void*  __restrict__ bsrc)     // PHASE1: f32 x[b][k]; PHASE2: unused
{
    constexpr int NCH = (KDIM / KSPLIT) / KCHUNK;   // 8 (gemm1) / 4 (gemm2)

    __shared__ __align__(16) __half Ash[2][MTILE * KCHUNK];   // 2 x 8 KB
    __shared__ __align__(16) __half Bsh[2][BATCH * KCHUNK];   // 2 x 4 KB

    const int tid  = threadIdx.x;
    const int wid  = tid >> 5;
    const int lane = tid & 31;

    const int n_base  = blockIdx.x * MTILE;
    const int k_begin = blockIdx.y * (KDIM / KSPLIT);

    // dequant mapping: thread -> (col arow, word pair j0=2*jp)
    const int arow = tid & 63;
    const int jp   = tid >> 6;               // 0..3
    const int j0   = jp * 2;
    const int ar7s = arow & 7;
    const int n_glob = n_base + arow;
    const uint32_t* pk = (const uint32_t*)packed
                       + (size_t)(k_begin >> 3) * NCOLS + n_glob;
    const float* scp = scales + n_glob;

    // B staging: 32 rows x 8 chunks of 16B, one per thread
    const int brow = tid >> 3;
    const int bcx  = tid & 7;
    const size_t boff0 = (size_t)brow * KDIM + k_begin + bcx * 8;   // in elements
    __half* bsp0 = &Bsh[0][brow * KCHUNK + ((bcx ^ (brow & 7)) * 8)];
    __half* bsp1 = &Bsh[1][brow * KCHUNK + ((bcx ^ (brow & 7)) * 8)];

    const float*  xf = (const float*)bsrc;
    const __half* xh = PHASE1 ? (const __half*)nullptr : g_acth;

    // slot registers (2-chunk-deep prefetch)
    uint32_t w0a, w1a, w0b, w1b;
    float    sca, scb;
    uint4    xva, xvb;

    auto loadW = [&](int c, uint32_t& w0, uint32_t& w1, float& sc) {
        w0 = pk[(size_t)(c * 8 + j0)     * NCOLS];
        w1 = pk[(size_t)(c * 8 + j0 + 1) * NCOLS];
        sc = scp[(size_t)((k_begin + c * KCHUNK) >> 7) * NCOLS];
    };
    auto loadB = [&](int c, uint4& xv) {
        const size_t off = boff0 + (size_t)c * KCHUNK;
        if (PHASE1) {
            float4 a = *(const float4*)(xf + off);
            float4 b = *(const float4*)(xf + off + 4);
            __half2 h0 = __float22half2_rn(make_float2(a.x, a.y));
            __half2 h1 = __float22half2_rn(make_float2(a.z, a.w));
            __half2 h2 = __float22half2_rn(make_float2(b.x, b.y));
            __half2 h3 = __float22half2_rn(make_float2(b.z, b.w));
            xv = make_uint4(*(uint32_t*)&h0, *(uint32_t*)&h1,
                            *(uint32_t*)&h2, *(uint32_t*)&h3);
        } else {
            xv = *(const uint4*)(xh + off);
        }
    };

    // ---- prefetch chunks 0,1 ----
    loadW(0, w0a, w1a, sca); loadB(0, xva);
    loadW(1, w0b, w1b, scb); loadB(1, xvb);

    float acc[2][4] = {};

    // MMA lane addressing (constant per thread)
    const uint32_t Abase0 = smem_u32(&Ash[0][0]);
    const uint32_t Bbase0 = smem_u32(&Bsh[0][0]);
    const int sub = lane >> 3, l7 = lane & 7;
    const int mrow = (wid & 3) * 16;
    const int nh   = wid >> 2;                  // 0/1: batch half
    const int ar   = mrow + l7 + (sub & 1) * 8;
    const int ar7  = ar & 7;
    const uint32_t a_row = (uint32_t)ar * (KCHUNK * 2);
    const int acx_off = sub >> 1;
    const int bn  = nh * 16 + l7 + (sub >> 1) * 8;
    const int bn7 = bn & 7;
    const uint32_t b_row = (uint32_t)bn * (KCHUNK * 2);
    const int bcx_off = sub & 1;

    auto dq_store = [&](int buf, uint32_t w0, uint32_t w1, float sc, uint4 xv) {
        *(uint4*)(buf ? bsp1 : bsp0) = xv;
        __half hs = __float2half_rn(sc * 16384.0f);   // exact pow2 fold
        uint32_t sf2 = (uint32_t)__half_as_ushort(hs) * 0x00010001u;
        uint32_t o[4];
        dq_word(w0, sf2, o);
        *(uint4*)(&Ash[buf][arow * KCHUNK + ((j0 ^ ar7s) * 8)]) =
            make_uint4(o[0], o[1], o[2], o[3]);
        dq_word(w1, sf2, o);
        *(uint4*)(&Ash[buf][arow * KCHUNK + (((j0 + 1) ^ ar7s) * 8)]) =
            make_uint4(o[0], o[1], o[2], o[3]);
    };
    auto compute = [&](int buf) {
        const uint32_t Ab = Abase0 + (uint32_t)buf * (MTILE * KCHUNK * 2);
        const uint32_t Bb = Bbase0 + (uint32_t)buf * (BATCH * KCHUNK * 2);
        #pragma unroll
        for (int ks = 0; ks < 4; ++ks) {
            uint32_t a[4], b[4];
            ldsm_x4(a[0], a[1], a[2], a[3],
                    Ab + a_row + (uint32_t)(((ks * 2 + acx_off) ^ ar7) << 4));
            ldsm_x4(b[0], b[1], b[2], b[3],
                    Bb + b_row + (uint32_t)(((ks * 2 + bcx_off) ^ bn7) << 4));
            mma_16816(acc[0], a, &b[0]);
            mma_16816(acc[1], a, &b[2]);
        }
    };

    #pragma unroll
    for (int cc = 0; cc < NCH; cc += 2) {
        // even chunk -> buffer 0 / slot A
        dq_store(0, w0a, w1a, sca, xva);
        if (cc + 2 < NCH) { loadW(cc + 2, w0a, w1a, sca); loadB(cc + 2, xva); }
        __syncthreads();
        compute(0);
        // odd chunk -> buffer 1 / slot B
        dq_store(1, w0b, w1b, scb, xvb);
        if (cc + 3 < NCH) { loadW(cc + 3, w0b, w1b, scb); loadB(cc + 3, xvb); }
        __syncthreads();
        compute(1);
    }

    // ---- epilogue: D fragments -> partials [n][b] ----
    float* outp = (PHASE1 ? &g_hpart[0][0] : &g_opart[0][0])
                  + (size_t)blockIdx.y * (NCOLS * BATCH);
    const int gq = lane >> 2, tq = lane & 3;
    const int nrow0 = n_base + mrow + gq;
    #pragma unroll
    for (int t = 0; t < 2; ++t) {
        const int bcol = nh * 16 + t * 8 + tq * 2;
        *(float2*)&outp[(size_t)nrow0 * BATCH + bcol]       = make_float2(acc[t][0], acc[t][1]);
        *(float2*)&outp[(size_t)(nrow0 + 8) * BATCH + bcol] = make_float2(acc[t][2], acc[t][3]);
    }
}

// ---------------- SwiGLU: reduce gemm1 partials -> act fp16 [b][i] -------
// grid = IDIM/8 = 256 blocks; 1 (i,b) item per thread, 16 independent loads.
__global__ void __launch_bounds__(256) swiglu_kernel() {
    __shared__ float s_act[8][33];
    const int i0 = blockIdx.x * 8;
    const int b  = threadIdx.x & 31;
    const int il = threadIdx.x >> 5;          // 0..7
    {
        const size_t ng = (size_t)(i0 + il) * BATCH + b;
        float hg = 0.f, hu = 0.f;
        #pragma unroll
        for (int s = 0; s < KSPLIT; ++s) {
            hg += g_hpart[s][ng];
            hu += g_hpart[s][ng + (size_t)IDIM * BATCH];
        }
        const float sig = 1.0f / (1.0f + __expf(-hg));
        s_act[il][b] = hg * sig * hu;
    }
    __syncthreads();
    // transpose write: half2 per thread -> [b][i0+2p]
    const int b2 = threadIdx.x >> 2;          // 0..63 -> but BATCH=32: use >>3? no:
    // 256 threads = 32 b x 4 half2-pairs
    const int bb = threadIdx.x >> 3;          // 0..31
    const int pp = threadIdx.x & 3;           // 0..3 (pair index), bit2 unused pad
    if ((threadIdx.x & 4) == 0) {
        __half2 h = __float22half2_rn(make_float2(s_act[pp * 2][bb], s_act[pp * 2 + 1][bb]));
        *(__half2*)&g_acth[(size_t)bb * IDIM + i0 + pp * 2] = h;
    }
    (void)b2;
}

// ---------------- reduce gemm2 partials [n][b] -> out [b][n] f32 ---------
// grid = NCOLS/8 = 512 blocks; 1 (n,b) item per thread, 8 independent loads.
__global__ void __launch_bounds__(256) reduce_out_kernel(float* __restrict__ out) {
    __shared__ float s_o[8][33];
    const int h0 = blockIdx.x * 8;
    const int b  = threadIdx.x & 31;
    const int hl = threadIdx.x >> 5;          // 0..7
    {
        const size_t ng = (size_t)(h0 + hl) * BATCH + b;
        float s = 0.f;
        #pragma unroll
        for (int sp = 0; sp < KSPLIT; ++sp)
            s += g_opart[sp][ng];
        s_o[hl][b] = s;
    }
    __syncthreads();
    // transpose write: 32 b rows x 8 cols, 1 per thread
    const int bb = threadIdx.x >> 3;          // 0..31
    const int h2 = threadIdx.x & 7;           // 0..7
    out[(size_t)bb * NCOLS + h0 + h2] =
        __half2float(__float2half_rn(s_o[h2][bb]));   // f16 grid like ref
}

// ---------------- launch --------------------------------------------------
extern "C" void kernel_launch(void* const* d_in, const int* in_sizes, int n_in,
                              void* d_out, int out_size) {
    const float* x   = (const float*)d_in[0];
    const int*   gup = (const int*)  d_in[1];
    const float* gus = (const float*)d_in[2];
    const int*   dwn = (const int*)  d_in[3];
    const float* dws = (const float*)d_in[4];
    float* out = (float*)d_out;

    gemm_mma_kernel<HDIM, true><<<dim3(NCOLS / MTILE, KSPLIT), 256>>>(gup, gus, x);

    swiglu_kernel<<<IDIM / 8, 256>>>();

    gemm_mma_kernel<IDIM, false><<<dim3(NCOLS / MTILE, KSPLIT), 256>>>(dwn, dws, nullptr);

    reduce_out_kernel<<<NCOLS / 8, 256>>>(out);
}